// round 10
// baseline (speedup 1.0000x reference)
#include <cuda_runtime.h>
#include <cuda_fp16.h>
#include <stdint.h>

#define NS 32
#define TT 2048
#define ND 1024
#define GRID 128
#define NTHREADS 512   // warps 0-7 = P (recurrent), 8-15 = Q (input GEMMs)
#define KTILES 8       // per-warp k-slice: 8 ktiles * 16 = 128; 8 warps = 1024
#define ROWBLK 32
#define SBLK 8
#define SGROUPS 4
#define NCHUNK ((TT - 2) / 3)   // 682 three-step chunks + 1 single step

#define ALPHA 0.1f
#define BETA  0.9f
#define A2C   (ALPHA * ALPHA)
#define ABC   (ALPHA * BETA)
#define BB    (BETA * BETA)
#define AB2   (2.0f * ALPHA * BETA)

__device__ __align__(16) __half g_hbuf[2][NS * ND];
__device__ float g_A2[ND * ND];
__device__ float g_A3[ND * ND];
__device__ __align__(256) volatile unsigned g_flags[SGROUPS][32];
__device__ unsigned g_bar_count;
__device__ unsigned g_bar_gen;

__device__ __forceinline__ void grid_barrier() {
    __syncthreads();
    if (threadIdx.x == 0) {
        unsigned gen = *((volatile unsigned*)&g_bar_gen);
        __threadfence();
        unsigned old = atomicAdd(&g_bar_count, 1u);
        if (old == GRID - 1) {
            g_bar_count = 0;
            __threadfence();
            atomicExch(&g_bar_gen, gen + 1u);
        } else {
            while (*((volatile unsigned*)&g_bar_gen) == gen) { }
        }
        __threadfence();
    }
    __syncthreads();
}

__device__ __forceinline__ void mma16816(float* d, const uint32_t* a,
                                         uint32_t b0, uint32_t b1) {
    asm volatile(
        "mma.sync.aligned.m16n8k16.row.col.f32.f16.f16.f32 "
        "{%0,%1,%2,%3}, {%4,%5,%6,%7}, {%8,%9}, {%0,%1,%2,%3};\n"
        : "+f"(d[0]), "+f"(d[1]), "+f"(d[2]), "+f"(d[3])
        : "r"(a[0]), "r"(a[1]), "r"(a[2]), "r"(a[3]), "r"(b0), "r"(b1));
}

__device__ __forceinline__ int hpos(int j) {
    int r = j & 15;
    return (j & ~15) + ((r & 6) << 1) + ((r >> 3) << 1) + (r & 1);
}

__device__ __forceinline__ unsigned flag_acquire(const volatile unsigned* p) {
    unsigned v;
    asm volatile("ld.global.acquire.gpu.u32 %0, [%1];"
                 : "=r"(v) : "l"((const unsigned*)p) : "memory");
    return v;
}

__device__ __forceinline__ void flag_release(volatile unsigned* p, unsigned v) {
    asm volatile("st.global.release.gpu.u32 [%0], %1;"
                 :: "l"((unsigned*)p), "r"(v) : "memory");
}

__device__ __forceinline__ void prefetch_l2(const void* p) {
    asm volatile("prefetch.global.L2 [%0];" :: "l"(p));
}

// Named barrier 1 over the 8 P warps (threads 0-255).
__device__ __forceinline__ void pbar() {
    asm volatile("bar.sync 1, 256;" ::: "memory");
}

__device__ __forceinline__ void load_afrag(uint32_t* f, const float* src,
                                           int row, int k0) {
    const float* p = src + (size_t)row * ND + k0;
    float2 v0 = *(const float2*)(p);
    float2 v1 = *(const float2*)(p + 8 * (size_t)ND);
    float2 v2 = *(const float2*)(p + 8);
    float2 v3 = *(const float2*)(p + 8 * (size_t)ND + 8);
    __half2 q0 = __floats2half2_rn(v0.x, v0.y);
    __half2 q1 = __floats2half2_rn(v1.x, v1.y);
    __half2 q2 = __floats2half2_rn(v2.x, v2.y);
    __half2 q3 = __floats2half2_rn(v3.x, v3.y);
    f[0] = *(uint32_t*)&q0; f[1] = *(uint32_t*)&q1;
    f[2] = *(uint32_t*)&q2; f[3] = *(uint32_t*)&q3;
}

__global__ __launch_bounds__(NTHREADS, 1) void rnn_kernel(
    const float* __restrict__ inp,   // [NS, TT, ND]
    const float* __restrict__ A,     // [ND, ND]
    const float* __restrict__ h0,    // [NS, ND]
    float* __restrict__ out)         // [NS, TT, ND]
{
    // Static: P psums (P1, P2, P3) = 24 KB.
    __shared__ float psumP[3][8][SBLK * ROWBLK];
    // Dynamic: A^3 frags (64 KB) + double-buffered Q psums (48 KB).
    extern __shared__ char dynsm[];
    uint4* smA3 = (uint4*)dynsm;
    float* qps  = (float*)(dynsm + 65536); // [(buf*3+arr)*8+qw]*256 + slot

    const int tid  = threadIdx.x;
    const int w    = tid >> 5;
    const int wk   = w & 7;          // k-slice id (shared by P/Q partner warps)
    const int lane = tid & 31;
    const int g    = lane >> 2;
    const int tig  = lane & 3;
    const bool isP = (w < 8);

    const int cta  = blockIdx.x;
    const int rb   = cta >> 2;
    const int sb   = cta & 3;
    const int row0 = rb * ROWBLK;
    const int s0   = sb * SBLK;

    // ---- Resident A fragments (k-split; same slice for P/Q partner) ----
    uint32_t afrag[KTILES][2][4];
#pragma unroll
    for (int kt = 0; kt < KTILES; kt++) {
        int k0 = (wk * KTILES + kt) * 16 + 2 * tig;
        load_afrag(afrag[kt][0], A, row0 + g, k0);
        load_afrag(afrag[kt][1], A, row0 + 16 + g, k0);
    }

    // ========== Phase 1a: A2 = A @ A (warps 0-7 compute; all sync) ==========
    for (int jj = 0; jj < 32; jj++) {
        const int jblk = sb * 32 + jj;
        const int j    = jblk * 8 + g;
        if (isP) {
            float d[2][4];
#pragma unroll
            for (int m = 0; m < 2; m++)
#pragma unroll
                for (int c = 0; c < 4; c++) d[m][c] = 0.0f;
#pragma unroll
            for (int kt = 0; kt < KTILES; kt++) {
                const int kb = (wk * KTILES + kt) * 16;
                float e0 = A[(size_t)(kb + 2 * tig)     * ND + j];
                float e1 = A[(size_t)(kb + 2 * tig + 1) * ND + j];
                float e2 = A[(size_t)(kb + 2 * tig + 8) * ND + j];
                float e3 = A[(size_t)(kb + 2 * tig + 9) * ND + j];
                __half2 hb0 = __floats2half2_rn(e0, e1);
                __half2 hb1 = __floats2half2_rn(e2, e3);
                mma16816(d[0], afrag[kt][0], *(uint32_t*)&hb0, *(uint32_t*)&hb1);
                mma16816(d[1], afrag[kt][1], *(uint32_t*)&hb0, *(uint32_t*)&hb1);
            }
#pragma unroll
            for (int m = 0; m < 2; m++)
#pragma unroll
                for (int c = 0; c < 4; c++) {
                    int i_loc = m * 16 + g + ((c >> 1) << 3);
                    int j_loc = tig * 2 + (c & 1);
                    psumP[0][w][j_loc * ROWBLK + i_loc] = d[m][c];
                }
        }
        __syncthreads();
        if (tid < 256) {
            int i_loc = tid & 31;
            int j_loc = tid >> 5;
            float s = 0.f;
#pragma unroll
            for (int ww = 0; ww < 8; ww++)
                s += psumP[0][ww][j_loc * ROWBLK + i_loc];
            g_A2[(size_t)(row0 + i_loc) * ND + jblk * 8 + j_loc] = s;
        }
        __syncthreads();
    }
    grid_barrier();

    // ---- Resident A^2 fragments ----
    uint32_t a2frag[KTILES][2][4];
#pragma unroll
    for (int kt = 0; kt < KTILES; kt++) {
        int k0 = (wk * KTILES + kt) * 16 + 2 * tig;
        load_afrag(a2frag[kt][0], g_A2, row0 + g, k0);
        load_afrag(a2frag[kt][1], g_A2, row0 + 16 + g, k0);
    }

    // ========== Phase 1b: A3 = A2 @ A ==========
    for (int jj = 0; jj < 32; jj++) {
        const int jblk = sb * 32 + jj;
        const int j    = jblk * 8 + g;
        if (isP) {
            float d[2][4];
#pragma unroll
            for (int m = 0; m < 2; m++)
#pragma unroll
                for (int c = 0; c < 4; c++) d[m][c] = 0.0f;
#pragma unroll
            for (int kt = 0; kt < KTILES; kt++) {
                const int kb = (wk * KTILES + kt) * 16;
                float e0 = A[(size_t)(kb + 2 * tig)     * ND + j];
                float e1 = A[(size_t)(kb + 2 * tig + 1) * ND + j];
                float e2 = A[(size_t)(kb + 2 * tig + 8) * ND + j];
                float e3 = A[(size_t)(kb + 2 * tig + 9) * ND + j];
                __half2 hb0 = __floats2half2_rn(e0, e1);
                __half2 hb1 = __floats2half2_rn(e2, e3);
                mma16816(d[0], a2frag[kt][0], *(uint32_t*)&hb0, *(uint32_t*)&hb1);
                mma16816(d[1], a2frag[kt][1], *(uint32_t*)&hb0, *(uint32_t*)&hb1);
            }
#pragma unroll
            for (int m = 0; m < 2; m++)
#pragma unroll
                for (int c = 0; c < 4; c++) {
                    int i_loc = m * 16 + g + ((c >> 1) << 3);
                    int j_loc = tig * 2 + (c & 1);
                    psumP[0][w][j_loc * ROWBLK + i_loc] = d[m][c];
                }
        }
        __syncthreads();
        if (tid < 256) {
            int i_loc = tid & 31;
            int j_loc = tid >> 5;
            float s = 0.f;
#pragma unroll
            for (int ww = 0; ww < 8; ww++)
                s += psumP[0][ww][j_loc * ROWBLK + i_loc];
            g_A3[(size_t)(row0 + i_loc) * ND + jblk * 8 + j_loc] = s;
        }
        __syncthreads();
    }
    grid_barrier();

    // ---- A^3 fragments into SMEM (P warps only; they are the readers) ----
    if (isP) {
#pragma unroll
        for (int kt = 0; kt < KTILES; kt++) {
            int k0 = (wk * KTILES + kt) * 16 + 2 * tig;
#pragma unroll
            for (int m = 0; m < 2; m++) {
                uint32_t tmp[4];
                load_afrag(tmp, g_A3, row0 + m * 16 + g, k0);
                smA3[((wk * KTILES + kt) * 2 + m) * 32 + lane] =
                    make_uint4(tmp[0], tmp[1], tmp[2], tmp[3]);
            }
        }
    }

    // ---- Per-thread ownership (valid for tid < 256 only) ----
    const int s_l  = tid >> 5;
    const int i_l  = tid & 31;
    const int s_gl = s0 + (s_l & 7);
    const int i_gl = row0 + i_l;
    const int e    = (s_l & 7) * ROWBLK + i_l;

    const float* inp_base = inp + (size_t)s_gl * TT * ND + i_gl;
    float* out_base       = out + (size_t)s_gl * TT * ND + i_gl;
    const int hslot = s_gl * ND + hpos(i_gl);

    const bool do_pf = (tid < 256) && ((tid & 31) == rb);
    const float* pf_base = inp + (size_t)s_gl * TT * ND + rb * 32;

    // ---- Production 0: h0 ----
    float hprev = 0.f;
    if (tid < 256) {
        hprev = h0[(size_t)s_gl * ND + i_gl];
        out_base[0] = hprev;
        g_hbuf[0][hslot] = __float2half_rn(hprev);
    }
    __syncthreads();
    if (tid == 0) flag_release(&g_flags[sb][rb], 1u);

    if (do_pf) {
#pragma unroll
        for (int r = 0; r < 6; r++) prefetch_l2(pf_base + (size_t)r * ND);
    }

    // x base for Q GEMMs (B operand rows = samples s0+g).
    const float* xq_base = inp + (size_t)(s0 + g) * TT * ND;

    // ---- Prologue: Q warps fill Q(0) into qbuf[0] ----
    if (!isP) {
        float q1a[2][4], q2a[2][4], q4a[2][4];
#pragma unroll
        for (int m = 0; m < 2; m++)
#pragma unroll
            for (int c = 0; c < 4; c++) { q1a[m][c]=0.f; q2a[m][c]=0.f; q4a[m][c]=0.f; }
#pragma unroll
        for (int kt = 0; kt < KTILES; kt++) {
            int kb = (wk * KTILES + kt) * 16 + 2 * tig;
            const float* xp = xq_base + kb;               // row 0
            const float* xn = xq_base + ND + kb;          // row 1
            float2 t0 = __ldcs((const float2*)xp);
            float2 t1 = __ldcs((const float2*)(xp + 8));
            float2 n0 = __ldcs((const float2*)xn);
            float2 n1 = __ldcs((const float2*)(xn + 8));
            __half2 ht0 = __floats2half2_rn(t0.x, t0.y);
            __half2 ht1 = __floats2half2_rn(t1.x, t1.y);
            __half2 hc0 = __floats2half2_rn(n0.x - BETA * t0.x, n0.y - BETA * t0.y);
            __half2 hc1 = __floats2half2_rn(n1.x - BETA * t1.x, n1.y - BETA * t1.y);
            uint32_t bt0 = *(uint32_t*)&ht0, bt1 = *(uint32_t*)&ht1;
            uint32_t bc0 = *(uint32_t*)&hc0, bc1 = *(uint32_t*)&hc1;
            mma16816(q1a[0], afrag[kt][0],  bt0, bt1);
            mma16816(q1a[1], afrag[kt][1],  bt0, bt1);
            mma16816(q2a[0], a2frag[kt][0], bt0, bt1);
            mma16816(q2a[1], a2frag[kt][1], bt0, bt1);
            mma16816(q4a[0], afrag[kt][0],  bc0, bc1);
            mma16816(q4a[1], afrag[kt][1],  bc0, bc1);
        }
#pragma unroll
        for (int m = 0; m < 2; m++)
#pragma unroll
            for (int c = 0; c < 4; c++) {
                int i_loc = m * 16 + g + ((c >> 1) << 3);
                int s_loc = tig * 2 + (c & 1);
                int slot = s_loc * ROWBLK + i_loc;
                qps[((0 * 3 + 0) * 8 + wk) * 256 + slot] = q1a[m][c];
                qps[((0 * 3 + 1) * 8 + wk) * 256 + slot] = q2a[m][c];
                qps[((0 * 3 + 2) * 8 + wk) * 256 + slot] = q4a[m][c];
            }
    }
    __syncthreads();

    // ================= Main loop: 682 triple-steps =================
    for (int s = 0; s < NCHUNK; s++) {
        const int ts = 3 * s;

        if (isP) {
            float xa = __ldcs(inp_base + (size_t)ts * ND);
            float xb = __ldcs(inp_base + (size_t)(ts + 1) * ND);
            float xc = __ldcs(inp_base + (size_t)(ts + 2) * ND);

            if (do_pf && ts + 8 < TT) {
                prefetch_l2(pf_base + (size_t)(ts + 6) * ND);
                prefetch_l2(pf_base + (size_t)(ts + 7) * ND);
                prefetch_l2(pf_base + (size_t)(ts + 8) * ND);
            }

            // ---- Poll (warp 0), broadcast via named barrier ----
            if (w == 0) {
                const volatile unsigned* f = &g_flags[sb][lane];
                unsigned v = flag_acquire(f);
                while (__ballot_sync(0xffffffffu, v < (unsigned)(s + 1))) {
                    if (v < (unsigned)(s + 1)) v = flag_acquire(f);
                }
            }
            pbar();

            const __half* hb = g_hbuf[s & 1];

            float p1a[2][4], p2a[2][4], p3a[2][4];
#pragma unroll
            for (int m = 0; m < 2; m++)
#pragma unroll
                for (int c = 0; c < 4; c++) { p1a[m][c]=0.f; p2a[m][c]=0.f; p3a[m][c]=0.f; }

#pragma unroll
            for (int kt = 0; kt < KTILES; kt++) {
                int koff = (wk * KTILES + kt) * 16 + tig * 4;
                uint2 b = *(const uint2*)(hb + (size_t)(s0 + g) * ND + koff);
                uint4 f0 = smA3[((wk * KTILES + kt) * 2 + 0) * 32 + lane];
                uint4 f1 = smA3[((wk * KTILES + kt) * 2 + 1) * 32 + lane];
                mma16816(p1a[0], afrag[kt][0],  b.x, b.y);
                mma16816(p1a[1], afrag[kt][1],  b.x, b.y);
                mma16816(p2a[0], a2frag[kt][0], b.x, b.y);
                mma16816(p2a[1], a2frag[kt][1], b.x, b.y);
                mma16816(p3a[0], (const uint32_t*)&f0, b.x, b.y);
                mma16816(p3a[1], (const uint32_t*)&f1, b.x, b.y);
            }

#pragma unroll
            for (int m = 0; m < 2; m++)
#pragma unroll
                for (int c = 0; c < 4; c++) {
                    int i_loc = m * 16 + g + ((c >> 1) << 3);
                    int s_loc = tig * 2 + (c & 1);
                    int slot = s_loc * ROWBLK + i_loc;
                    psumP[0][w][slot] = p1a[m][c];
                    psumP[1][w][slot] = p2a[m][c];
                    psumP[2][w][slot] = p3a[m][c];
                }
            pbar();

            const float* qb = qps + (size_t)(s & 1) * 3 * 8 * 256;
            float P1 = 0.f, R2 = 0.f, R3 = 0.f, Q4 = 0.f;
#pragma unroll
            for (int ww = 0; ww < 8; ww++) {
                P1 += psumP[0][ww][e];
                R2 += psumP[1][ww][e];
                R3 += psumP[2][ww][e];
            }
#pragma unroll
            for (int ww = 0; ww < 8; ww++) {
                R2 += qb[(0 * 8 + ww) * 256 + e];
                R3 += qb[(1 * 8 + ww) * 256 + e];
                Q4 += qb[(2 * 8 + ww) * 256 + e];
            }

            float h1  = BETA * hprev + ALPHA * (P1 + xa);
            float h2  = BETA * h1 + ABC * P1 + A2C * R2 + ALPHA * xb;
            float Ah2 = BB * P1 + AB2 * R2 + A2C * R3 + ALPHA * Q4;
            float h3  = BETA * h2 + ALPHA * (Ah2 + xc);
            hprev = h3;

            g_hbuf[(s + 1) & 1][hslot] = __float2half_rn(h3);
            pbar();
            if (tid == 0) flag_release(&g_flags[sb][rb], (unsigned)(s + 2));

            __stcs(out_base + (size_t)(ts + 1) * ND, h1);
            __stcs(out_base + (size_t)(ts + 2) * ND, h2);
            __stcs(out_base + (size_t)(ts + 3) * ND, h3);
        } else {
            // ---- Q warps: compute Q(s+1) into qbuf[(s+1)&1] ----
            const int tn = 3 * (s + 1);
            float q1a[2][4], q2a[2][4], q4a[2][4];
#pragma unroll
            for (int m = 0; m < 2; m++)
#pragma unroll
                for (int c = 0; c < 4; c++) { q1a[m][c]=0.f; q2a[m][c]=0.f; q4a[m][c]=0.f; }
#pragma unroll
            for (int kt = 0; kt < KTILES; kt++) {
                int kb = (wk * KTILES + kt) * 16 + 2 * tig;
                const float* xp = xq_base + (size_t)tn * ND + kb;
                const float* xn = xq_base + (size_t)(tn + 1) * ND + kb;
                float2 t0 = __ldcs((const float2*)xp);
                float2 t1 = __ldcs((const float2*)(xp + 8));
                float2 n0 = __ldcs((const float2*)xn);
                float2 n1 = __ldcs((const float2*)(xn + 8));
                __half2 ht0 = __floats2half2_rn(t0.x, t0.y);
                __half2 ht1 = __floats2half2_rn(t1.x, t1.y);
                __half2 hc0 = __floats2half2_rn(n0.x - BETA * t0.x, n0.y - BETA * t0.y);
                __half2 hc1 = __floats2half2_rn(n1.x - BETA * t1.x, n1.y - BETA * t1.y);
                uint32_t bt0 = *(uint32_t*)&ht0, bt1 = *(uint32_t*)&ht1;
                uint32_t bc0 = *(uint32_t*)&hc0, bc1 = *(uint32_t*)&hc1;
                mma16816(q1a[0], afrag[kt][0],  bt0, bt1);
                mma16816(q1a[1], afrag[kt][1],  bt0, bt1);
                mma16816(q2a[0], a2frag[kt][0], bt0, bt1);
                mma16816(q2a[1], a2frag[kt][1], bt0, bt1);
                mma16816(q4a[0], afrag[kt][0],  bc0, bc1);
                mma16816(q4a[1], afrag[kt][1],  bc0, bc1);
            }
            float* qb = qps + (size_t)((s + 1) & 1) * 3 * 8 * 256;
#pragma unroll
            for (int m = 0; m < 2; m++)
#pragma unroll
                for (int c = 0; c < 4; c++) {
                    int i_loc = m * 16 + g + ((c >> 1) << 3);
                    int s_loc = tig * 2 + (c & 1);
                    int slot = s_loc * ROWBLK + i_loc;
                    qb[(0 * 8 + wk) * 256 + slot] = q1a[m][c];
                    qb[(1 * 8 + wk) * 256 + slot] = q2a[m][c];
                    qb[(2 * 8 + wk) * 256 + slot] = q4a[m][c];
                }
        }
        __syncthreads();   // swap Q double-buffer; both roles converge
    }

    // ================= Epilogue: final single step t = TT-1 =================
    if (isP) {
        const int s  = NCHUNK;          // 682
        const int ts = 3 * s;           // 2046
        float xa = __ldcs(inp_base + (size_t)ts * ND);

        if (w == 0) {
            const volatile unsigned* f = &g_flags[sb][lane];
            unsigned v = flag_acquire(f);
            while (__ballot_sync(0xffffffffu, v < (unsigned)(s + 1))) {
                if (v < (unsigned)(s + 1)) v = flag_acquire(f);
            }
        }
        pbar();

        const __half* hb = g_hbuf[s & 1];
        float d1[2][4];
#pragma unroll
        for (int m = 0; m < 2; m++)
#pragma unroll
            for (int c = 0; c < 4; c++) d1[m][c] = 0.f;
#pragma unroll
        for (int kt = 0; kt < KTILES; kt++) {
            int koff = (wk * KTILES + kt) * 16 + tig * 4;
            uint2 b = *(const uint2*)(hb + (size_t)(s0 + g) * ND + koff);
            mma16816(d1[0], afrag[kt][0], b.x, b.y);
            mma16816(d1[1], afrag[kt][1], b.x, b.y);
        }
#pragma unroll
        for (int m = 0; m < 2; m++)
#pragma unroll
            for (int c = 0; c < 4; c++) {
                int i_loc = m * 16 + g + ((c >> 1) << 3);
                int s_loc = tig * 2 + (c & 1);
                psumP[0][w][s_loc * ROWBLK + i_loc] = d1[m][c];
            }
        pbar();

        float P1 = 0.f;
#pragma unroll
        for (int ww = 0; ww < 8; ww++) P1 += psumP[0][ww][e];

        float h1 = BETA * hprev + ALPHA * (P1 + xa);
        __stcs(out_base + (size_t)(ts + 1) * ND, h1);
    }

    // ---- Cleanup so graph replays start from flags == 0 ----
    grid_barrier();
    if (tid == 0) g_flags[sb][rb] = 0u;
}

extern "C" void kernel_launch(void* const* d_in, const int* in_sizes, int n_in,
                              void* d_out, int out_size) {
    const float* inp = (const float*)d_in[0];
    const float* A   = (const float*)d_in[1];
    const float* h0  = (const float*)d_in[2];
    float* out       = (float*)d_out;
    cudaFuncSetAttribute(rnn_kernel,
                         cudaFuncAttributeMaxDynamicSharedMemorySize, 114688);
    rnn_kernel<<<GRID, NTHREADS, 114688>>>(inp, A, h0, out);
}

// round 11
// speedup vs baseline: 1.4465x; 1.4465x over previous
#include <cuda_runtime.h>
#include <cuda_fp16.h>
#include <stdint.h>

#define NS 32
#define TT 2048
#define ND 1024
#define GRID 128
#define NTHREADS 256
#define NWARPS 8
#define KTILES 8     // 8 warps * 8 ktiles * 16 = 1024 = K
#define ROWBLK 32    // A rows per CTA
#define SBLK 8       // samples per CTA
#define SGROUPS 4

#define ALPHA 0.1f
#define BETA  0.9f
#define A2C   (ALPHA * ALPHA)
#define ABC   (ALPHA * BETA)

// Double-buffered fp16 hidden state, pre-swizzled mma-B layout.
__device__ __align__(16) __half g_hbuf[2][NS * ND];
// A@A (row-major fp32), computed once per launch in phase 1.
__device__ float g_A2[ND * ND];
// Producer flags: g_flags[sb][rb] = completed productions by CTA (rb, sb).
__device__ __align__(256) volatile unsigned g_flags[SGROUPS][32];
// Sense-reversing grid barrier (phase transitions + cleanup only).
__device__ unsigned g_bar_count;
__device__ unsigned g_bar_gen;

__device__ __forceinline__ void grid_barrier() {
    __syncthreads();
    if (threadIdx.x == 0) {
        unsigned gen = *((volatile unsigned*)&g_bar_gen);
        __threadfence();
        unsigned old = atomicAdd(&g_bar_count, 1u);
        if (old == GRID - 1) {
            g_bar_count = 0;
            __threadfence();
            atomicExch(&g_bar_gen, gen + 1u);
        } else {
            while (*((volatile unsigned*)&g_bar_gen) == gen) { }
        }
        __threadfence();
    }
    __syncthreads();
}

__device__ __forceinline__ void mma16816(float* d, const uint32_t* a,
                                         uint32_t b0, uint32_t b1) {
    asm volatile(
        "mma.sync.aligned.m16n8k16.row.col.f32.f16.f16.f32 "
        "{%0,%1,%2,%3}, {%4,%5,%6,%7}, {%8,%9}, {%0,%1,%2,%3};\n"
        : "+f"(d[0]), "+f"(d[1]), "+f"(d[2]), "+f"(d[3])
        : "r"(a[0]), "r"(a[1]), "r"(a[2]), "r"(a[3]), "r"(b0), "r"(b1));
}

// Swizzled position of logical element j (per 16-block order 0,1,8,9,2,3,...).
__device__ __forceinline__ int hpos(int j) {
    int r = j & 15;
    return (j & ~15) + ((r & 6) << 1) + ((r >> 3) << 1) + (r & 1);
}

__device__ __forceinline__ unsigned flag_acquire(const volatile unsigned* p) {
    unsigned v;
    asm volatile("ld.global.acquire.gpu.u32 %0, [%1];"
                 : "=r"(v) : "l"((const unsigned*)p) : "memory");
    return v;
}

__device__ __forceinline__ void flag_release(volatile unsigned* p, unsigned v) {
    asm volatile("st.global.release.gpu.u32 [%0], %1;"
                 :: "l"((unsigned*)p), "r"(v) : "memory");
}

__device__ __forceinline__ void prefetch_l2(const void* p) {
    asm volatile("prefetch.global.L2 [%0];" :: "l"(p));
}

__device__ __forceinline__ void load_afrag(uint32_t* f, const float* src,
                                           int row, int k0) {
    const float* p = src + (size_t)row * ND + k0;
    float2 v0 = *(const float2*)(p);
    float2 v1 = *(const float2*)(p + 8 * (size_t)ND);
    float2 v2 = *(const float2*)(p + 8);
    float2 v3 = *(const float2*)(p + 8 * (size_t)ND + 8);
    __half2 q0 = __floats2half2_rn(v0.x, v0.y);
    __half2 q1 = __floats2half2_rn(v1.x, v1.y);
    __half2 q2 = __floats2half2_rn(v2.x, v2.y);
    __half2 q3 = __floats2half2_rn(v3.x, v3.y);
    f[0] = *(uint32_t*)&q0; f[1] = *(uint32_t*)&q1;
    f[2] = *(uint32_t*)&q2; f[3] = *(uint32_t*)&q3;
}

__global__ __launch_bounds__(NTHREADS, 1) void rnn_kernel(
    const float* __restrict__ inp,   // [NS, TT, ND]
    const float* __restrict__ A,     // [ND, ND]
    const float* __restrict__ h0,    // [NS, ND]
    float* __restrict__ out)         // [NS, TT, ND]
{
    __shared__ float psum1[NWARPS][SBLK * ROWBLK];  // 8 KB
    __shared__ float psum2[NWARPS][SBLK * ROWBLK];  // 8 KB

    const int tid  = threadIdx.x;
    const int w    = tid >> 5;
    const int lane = tid & 31;
    const int g    = lane >> 2;
    const int tig  = lane & 3;

    const int cta  = blockIdx.x;
    const int rb   = cta >> 2;        // 32 row blocks
    const int sb   = cta & 3;         // 4 sample groups
    const int row0 = rb * ROWBLK;
    const int s0   = sb * SBLK;

    // ---- Resident A fragments (k-split across warps) ----
    uint32_t afrag[KTILES][2][4];
#pragma unroll
    for (int kt = 0; kt < KTILES; kt++) {
        int k0 = (w * KTILES + kt) * 16 + 2 * tig;
        load_afrag(afrag[kt][0], A, row0 + g, k0);
        load_afrag(afrag[kt][1], A, row0 + 16 + g, k0);
    }

    // ========== Phase 1: A2 = A @ A, all 128 CTAs, j-split by sb ==========
    for (int jj = 0; jj < 32; jj++) {
        const int jblk = sb * 32 + jj;
        const int j    = jblk * 8 + g;
        float d[2][4];
#pragma unroll
        for (int m = 0; m < 2; m++)
#pragma unroll
            for (int c = 0; c < 4; c++) d[m][c] = 0.0f;

#pragma unroll
        for (int kt = 0; kt < KTILES; kt++) {
            const int kb = (w * KTILES + kt) * 16;
            float e0 = A[(size_t)(kb + 2 * tig)     * ND + j];
            float e1 = A[(size_t)(kb + 2 * tig + 1) * ND + j];
            float e2 = A[(size_t)(kb + 2 * tig + 8) * ND + j];
            float e3 = A[(size_t)(kb + 2 * tig + 9) * ND + j];
            __half2 hb0 = __floats2half2_rn(e0, e1);
            __half2 hb1 = __floats2half2_rn(e2, e3);
            uint32_t b0 = *(uint32_t*)&hb0;
            uint32_t b1 = *(uint32_t*)&hb1;
            mma16816(d[0], afrag[kt][0], b0, b1);
            mma16816(d[1], afrag[kt][1], b0, b1);
        }
#pragma unroll
        for (int m = 0; m < 2; m++)
#pragma unroll
            for (int c = 0; c < 4; c++) {
                int i_loc = m * 16 + g + ((c >> 1) << 3);
                int j_loc = tig * 2 + (c & 1);
                psum1[w][j_loc * ROWBLK + i_loc] = d[m][c];
            }
        __syncthreads();
        {
            int i_loc = tid & 31;
            int j_loc = tid >> 5;
            float s = 0.f;
#pragma unroll
            for (int ww = 0; ww < NWARPS; ww++)
                s += psum1[ww][j_loc * ROWBLK + i_loc];
            g_A2[(size_t)(row0 + i_loc) * ND + jblk * 8 + j_loc] = s;
        }
        __syncthreads();
    }
    grid_barrier();

    // ---- Resident A^2 fragments ----
    uint32_t a2frag[KTILES][2][4];
#pragma unroll
    for (int kt = 0; kt < KTILES; kt++) {
        int k0 = (w * KTILES + kt) * 16 + 2 * tig;
        load_afrag(a2frag[kt][0], g_A2, row0 + g, k0);
        load_afrag(a2frag[kt][1], g_A2, row0 + 16 + g, k0);
    }

    // ---- Per-thread state ownership: 1 element each ----
    const int s_l  = tid >> 5;            // 0..7
    const int i_l  = tid & 31;            // 0..31
    const int s_gl = s0 + s_l;
    const int i_gl = row0 + i_l;
    const int e    = s_l * ROWBLK + i_l;

    const float* inp_base = inp + (size_t)s_gl * TT * ND + i_gl;
    float* out_base       = out + (size_t)s_gl * TT * ND + i_gl;
    const int hslot = s_gl * ND + hpos(i_gl);

    // Dedup prefetch: thread (tid&31)==rb covers line rb of 8 sample rows.
    const bool do_pf = ((tid & 31) == rb);
    const float* pf_base = inp + (size_t)(s0 + (tid >> 5)) * TT * ND + rb * 32;

    // ---- Production 0: h0 ----
    float hprev = h0[(size_t)s_gl * ND + i_gl];
    out_base[0] = hprev;
    g_hbuf[0][hslot] = __float2half_rn(hprev);
    __syncthreads();
    if (tid == 0) flag_release(&g_flags[sb][rb], 1u);

    // Warm prefetch for chunk 0 (rows ts=0,1).
    if (do_pf) {
        prefetch_l2(pf_base);
        prefetch_l2(pf_base + ND);
    }

    // x base for the Q GEMM (B operand rows = samples s0+g).
    const float* xq_base = inp + (size_t)(s0 + g) * TT * ND;

    // ================= Main loop: 1023 double-steps =================
    for (int s = 0; s < (TT - 2) / 2; s++) {
        const int ts = 2 * s;   // produces h[ts+1], h[ts+2] from h[ts]

        float xa = __ldcs(inp_base + (size_t)ts * ND);
        float xb = __ldcs(inp_base + (size_t)(ts + 1) * ND);

        float d1[2][4];   // A h
        float d2[2][4];   // A^2 h + A x_ts   (both carry alpha^2)
#pragma unroll
        for (int m = 0; m < 2; m++)
#pragma unroll
            for (int c = 0; c < 4; c++) { d1[m][c] = 0.f; d2[m][c] = 0.f; }

        // ---- Load + convert Q x-data (ALL warps; L2 hits via prefetch) ----
        uint32_t btA[KTILES], btB[KTILES];
#pragma unroll
        for (int kt = 0; kt < KTILES; kt++) {
            int kb = (w * KTILES + kt) * 16 + 2 * tig;
            const float* xp = xq_base + (size_t)ts * ND + kb;
            float2 v0 = __ldcs((const float2*)xp);
            float2 v1 = __ldcs((const float2*)(xp + 8));
            __half2 hq0 = __floats2half2_rn(v0.x, v0.y);
            __half2 hq1 = __floats2half2_rn(v1.x, v1.y);
            btA[kt] = *(uint32_t*)&hq0;
            btB[kt] = *(uint32_t*)&hq1;
        }

        // Prefetch next chunk's x rows into L2 (deduplicated across CTAs).
        if (do_pf && ts + 2 < TT) {
            prefetch_l2(pf_base + (size_t)(ts + 2) * ND);
            prefetch_l2(pf_base + (size_t)(ts + 3) * ND);
        }

        // ---- Warp 0 polls IMMEDIATELY (Q deferred); warps 1-7 do Q now ----
        if (w == 0) {
            const volatile unsigned* f = &g_flags[sb][lane];
            unsigned v = flag_acquire(f);
            while (__ballot_sync(0xffffffffu, v < (unsigned)(s + 1))) {
                if (v < (unsigned)(s + 1)) v = flag_acquire(f);
            }
        } else {
#pragma unroll
            for (int kt = 0; kt < KTILES; kt++) {
                mma16816(d2[0], afrag[kt][0], btA[kt], btB[kt]);
                mma16816(d2[1], afrag[kt][1], btA[kt], btB[kt]);
            }
        }
        __syncthreads();

        const __half* hb = g_hbuf[s & 1];

        // Warp 0's deferred Q: independent of hb, executes in the L2-latency
        // shadow of its hb loads below.
        if (w == 0) {
#pragma unroll
            for (int kt = 0; kt < KTILES; kt++) {
                mma16816(d2[0], afrag[kt][0], btA[kt], btB[kt]);
                mma16816(d2[1], afrag[kt][1], btA[kt], btB[kt]);
            }
        }

        // ---- P1 = A h, P2 += A^2 h (shared B fragments) ----
#pragma unroll
        for (int kt = 0; kt < KTILES; kt++) {
            int koff = (w * KTILES + kt) * 16 + tig * 4;
            uint2 b = *(const uint2*)(hb + (size_t)(s0 + g) * ND + koff);
            mma16816(d1[0], afrag[kt][0],  b.x, b.y);
            mma16816(d1[1], afrag[kt][1],  b.x, b.y);
            mma16816(d2[0], a2frag[kt][0], b.x, b.y);
            mma16816(d2[1], a2frag[kt][1], b.x, b.y);
        }

        // ---- cross-warp reduction ----
#pragma unroll
        for (int m = 0; m < 2; m++)
#pragma unroll
            for (int c = 0; c < 4; c++) {
                int i_loc = m * 16 + g + ((c >> 1) << 3);
                int s_loc = tig * 2 + (c & 1);
                psum1[w][s_loc * ROWBLK + i_loc] = d1[m][c];
                psum2[w][s_loc * ROWBLK + i_loc] = d2[m][c];
            }
        __syncthreads();

        float P1 = 0.f, D2 = 0.f;
#pragma unroll
        for (int ww = 0; ww < NWARPS; ww++) {
            P1 += psum1[ww][e];
            D2 += psum2[ww][e];
        }

        float h1 = BETA * hprev + ALPHA * (P1 + xa);
        float h2 = BETA * h1 + ABC * P1 + A2C * D2 + ALPHA * xb;
        hprev = h2;

        // Publish state first (critical path), outputs after the release.
        g_hbuf[(s + 1) & 1][hslot] = __float2half_rn(h2);
        __syncthreads();
        if (tid == 0) flag_release(&g_flags[sb][rb], (unsigned)(s + 2));

        __stcs(out_base + (size_t)(ts + 1) * ND, h1);
        __stcs(out_base + (size_t)(ts + 2) * ND, h2);
    }

    // ================= Epilogue: final single step t = TT-1 =================
    {
        const int s  = (TT - 2) / 2;   // 1023
        const int ts = 2 * s;          // 2046
        float xa = __ldcs(inp_base + (size_t)ts * ND);

        if (w == 0) {
            const volatile unsigned* f = &g_flags[sb][lane];
            unsigned v = flag_acquire(f);
            while (__ballot_sync(0xffffffffu, v < (unsigned)(s + 1))) {
                if (v < (unsigned)(s + 1)) v = flag_acquire(f);
            }
        }
        __syncthreads();

        const __half* hb = g_hbuf[s & 1];
        float d1[2][4];
#pragma unroll
        for (int m = 0; m < 2; m++)
#pragma unroll
            for (int c = 0; c < 4; c++) d1[m][c] = 0.f;

#pragma unroll
        for (int kt = 0; kt < KTILES; kt++) {
            int koff = (w * KTILES + kt) * 16 + tig * 4;
            uint2 b = *(const uint2*)(hb + (size_t)(s0 + g) * ND + koff);
            mma16816(d1[0], afrag[kt][0], b.x, b.y);
            mma16816(d1[1], afrag[kt][1], b.x, b.y);
        }
#pragma unroll
        for (int m = 0; m < 2; m++)
#pragma unroll
            for (int c = 0; c < 4; c++) {
                int i_loc = m * 16 + g + ((c >> 1) << 3);
                int s_loc = tig * 2 + (c & 1);
                psum1[w][s_loc * ROWBLK + i_loc] = d1[m][c];
            }
        __syncthreads();

        float P1 = 0.f;
#pragma unroll
        for (int ww = 0; ww < NWARPS; ww++) P1 += psum1[ww][e];

        float h1 = BETA * hprev + ALPHA * (P1 + xa);
        __stcs(out_base + (size_t)(ts + 1) * ND, h1);
    }

    // ---- Cleanup so graph replays start from flags == 0 ----
    grid_barrier();
    if (tid == 0) g_flags[sb][rb] = 0u;
}

extern "C" void kernel_launch(void* const* d_in, const int* in_sizes, int n_in,
                              void* d_out, int out_size) {
    const float* inp = (const float*)d_in[0];
    const float* A   = (const float*)d_in[1];
    const float* h0  = (const float*)d_in[2];
    float* out       = (float*)d_out;
    rnn_kernel<<<GRID, NTHREADS>>>(inp, A, h0, out);
}